// round 5
// baseline (speedup 1.0000x reference)
#include <cuda_runtime.h>
#include <cuda_bf16.h>
#include <cstdint>

// Problem constants (fixed by the reference generator)
#define F_DIM 16
#define B_GRAPHS 8
#define NVALS 9               // base + 8 segment dots
#define ACC_BLOCKS 2048
#define ACC_THREADS 256

// Per-block partials, transposed: g_partials[k][block]. Fully rewritten each
// launch -> no zeroing needed.
__device__ float g_partials[NVALS][ACC_BLOCKS];
// Ticket counter: starts 0 at module load; last block resets it to 0 every
// launch -> deterministic across graph replays.
__device__ unsigned int g_ticket;

__global__ __launch_bounds__(ACC_THREADS) void fused_kernel(
    const float* __restrict__ inp,
    const float* __restrict__ tgt,
    const int* __restrict__ batch,
    float* __restrict__ out,
    int n)
{
    float base = 0.0f;
    float dots[B_GRAPHS];
#pragma unroll
    for (int b = 0; b < B_GRAPHS; b++) dots[b] = 0.0f;

    const float4* inp4 = reinterpret_cast<const float4*>(inp);
    const float4* tgt4 = reinterpret_cast<const float4*>(tgt);
    const int2*   bat2 = reinterpret_cast<const int2*>(batch);

    const int tid    = blockIdx.x * blockDim.x + threadIdx.x;
    const int stride = gridDim.x * blockDim.x;
    const int pairs  = n >> 1;   // rows processed two at a time

    for (int p = tid; p < pairs; p += stride) {
        const float4* a = inp4 + (size_t)p * 8;   // rows 2p, 2p+1 (8 float4)
        const float4* t = tgt4 + (size_t)p * 8;

        float4 ax[8], tx[8];
#pragma unroll
        for (int j = 0; j < 8; j++) ax[j] = a[j];
#pragma unroll
        for (int j = 0; j < 8; j++) tx[j] = t[j];
        int2 bb = bat2[p];

        float sq = 0.0f, dot0 = 0.0f, dot1 = 0.0f;
#pragma unroll
        for (int j = 0; j < 8; j++) {
            float4 x = ax[j], y = tx[j];
            sq = fmaf(x.x, x.x, sq); sq = fmaf(x.y, x.y, sq);
            sq = fmaf(x.z, x.z, sq); sq = fmaf(x.w, x.w, sq);
            sq = fmaf(y.x, y.x, sq); sq = fmaf(y.y, y.y, sq);
            sq = fmaf(y.z, y.z, sq); sq = fmaf(y.w, y.w, sq);
            float d = 0.0f;
            d = fmaf(x.x, y.x, d); d = fmaf(x.y, y.y, d);
            d = fmaf(x.z, y.z, d); d = fmaf(x.w, y.w, d);
            if (j < 4) dot0 += d; else dot1 += d;
        }
        base += sq;

        int b0 = bb.x & (B_GRAPHS - 1);
        int b1 = bb.y & (B_GRAPHS - 1);
        // predicated adds (unrolled) — avoids local-memory spill
#pragma unroll
        for (int b = 0; b < B_GRAPHS; b++) {
            if (b0 == b) dots[b] += dot0;
            if (b1 == b) dots[b] += dot1;
        }
    }

    // odd-row tail (n always even here, but stay correct)
    if ((n & 1) && tid == 0) {
        int i = n - 1;
        const float4* a = inp4 + (size_t)i * 4;
        const float4* t = tgt4 + (size_t)i * 4;
        float sq = 0.0f, d = 0.0f;
#pragma unroll
        for (int j = 0; j < 4; j++) {
            float4 x = a[j], y = t[j];
            sq = fmaf(x.x, x.x, sq); sq = fmaf(x.y, x.y, sq);
            sq = fmaf(x.z, x.z, sq); sq = fmaf(x.w, x.w, sq);
            sq = fmaf(y.x, y.x, sq); sq = fmaf(y.y, y.y, sq);
            sq = fmaf(y.z, y.z, sq); sq = fmaf(y.w, y.w, sq);
            d  = fmaf(x.x, y.x, d);  d  = fmaf(x.y, y.y, d);
            d  = fmaf(x.z, y.z, d);  d  = fmaf(x.w, y.w, d);
        }
        base += sq;
        int b0 = batch[i] & (B_GRAPHS - 1);
#pragma unroll
        for (int b = 0; b < B_GRAPHS; b++)
            if (b0 == b) dots[b] += d;
    }

    // ----- block reduce of the 9 values -----
    float vals[NVALS];
    vals[0] = base;
#pragma unroll
    for (int b = 0; b < B_GRAPHS; b++) vals[b + 1] = dots[b];

#pragma unroll
    for (int k = 0; k < NVALS; k++) {
#pragma unroll
        for (int off = 16; off > 0; off >>= 1)
            vals[k] += __shfl_down_sync(0xFFFFFFFFu, vals[k], off);
    }

    __shared__ float smem[ACC_THREADS / 32][NVALS];
    __shared__ int s_is_last;
    int warp = threadIdx.x >> 5;
    int lane = threadIdx.x & 31;
    if (lane == 0) {
#pragma unroll
        for (int k = 0; k < NVALS; k++) smem[warp][k] = vals[k];
    }
    __syncthreads();

    if (threadIdx.x == 0) {
        float o[NVALS];
#pragma unroll
        for (int k = 0; k < NVALS; k++) o[k] = smem[0][k];
#pragma unroll
        for (int w = 1; w < ACC_THREADS / 32; w++) {
#pragma unroll
            for (int k = 0; k < NVALS; k++) o[k] += smem[w][k];
        }
#pragma unroll
        for (int k = 0; k < NVALS; k++)
            g_partials[k][blockIdx.x] = o[k];

        __threadfence();
        unsigned int ticket = atomicAdd(&g_ticket, 1u);
        s_is_last = (ticket == (unsigned)(gridDim.x - 1)) ? 1 : 0;
    }
    __syncthreads();

    if (!s_is_last) return;

    // ----- last block: reduce all partials (coalesced float4 reads) -----
    __threadfence();   // acquire side of the ticket handshake
    float fv[NVALS];
#pragma unroll
    for (int k = 0; k < NVALS; k++) fv[k] = 0.0f;

    // ACC_BLOCKS floats per component, 256 threads x float4 x 2 iterations
    for (int r4 = threadIdx.x; r4 < ACC_BLOCKS / 4; r4 += ACC_THREADS) {
#pragma unroll
        for (int k = 0; k < NVALS; k++) {
            float4 v = reinterpret_cast<const float4*>(g_partials[k])[r4];
            fv[k] += (v.x + v.y) + (v.z + v.w);
        }
    }

#pragma unroll
    for (int k = 0; k < NVALS; k++) {
#pragma unroll
        for (int off = 16; off > 0; off >>= 1)
            fv[k] += __shfl_down_sync(0xFFFFFFFFu, fv[k], off);
    }

    __syncthreads();   // smem reuse
    if (lane == 0) {
#pragma unroll
        for (int k = 0; k < NVALS; k++) smem[warp][k] = fv[k];
    }
    __syncthreads();

    if (threadIdx.x == 0) {
        float acc[NVALS];
#pragma unroll
        for (int k = 0; k < NVALS; k++) acc[k] = smem[0][k];
#pragma unroll
        for (int w = 1; w < ACC_THREADS / 32; w++) {
#pragma unroll
            for (int k = 0; k < NVALS; k++) acc[k] += smem[w][k];
        }
        // min over all 2^B sign combos == base - 2 * sum_b |dot_b|
        float s = 0.0f;
#pragma unroll
        for (int b = 0; b < B_GRAPHS; b++) s += fabsf(acc[b + 1]);
        out[0] = acc[0] - 2.0f * s;
        g_ticket = 0u;   // reset for next graph replay
    }
}

extern "C" void kernel_launch(void* const* d_in, const int* in_sizes, int n_in,
                              void* d_out, int out_size)
{
    const float* inp   = (const float*)d_in[0];
    const float* tgt   = (const float*)d_in[1];
    const int*   batch = (const int*)d_in[2];
    float* out = (float*)d_out;

    int n = in_sizes[2];  // number of nodes (batch vector length)

    fused_kernel<<<ACC_BLOCKS, ACC_THREADS>>>(inp, tgt, batch, out, n);
}

// round 6
// speedup vs baseline: 1.5065x; 1.5065x over previous
#include <cuda_runtime.h>
#include <cuda_bf16.h>
#include <cstdint>

// Problem constants (fixed by the reference generator)
#define F_DIM 16
#define B_GRAPHS 8
#define NVALS 9               // base + 8 segment dots
#define ACC_BLOCKS 2048
#define ACC_THREADS 256

// Per-block partials, transposed: g_partials[k][block]. Fully rewritten each
// launch -> no zeroing needed.
__device__ float g_partials[NVALS][ACC_BLOCKS];
// Ticket counter: starts 0 at module load; last block resets it to 0 every
// launch -> deterministic across graph replays.
__device__ unsigned int g_ticket;

__global__ __launch_bounds__(ACC_THREADS) void fused_kernel(
    const float* __restrict__ inp,
    const float* __restrict__ tgt,
    const int* __restrict__ batch,
    float* __restrict__ out,
    int n)
{
    float base = 0.0f;
    float dots[B_GRAPHS];
#pragma unroll
    for (int b = 0; b < B_GRAPHS; b++) dots[b] = 0.0f;

    const float4* __restrict__ inp4 = reinterpret_cast<const float4*>(inp);
    const float4* __restrict__ tgt4 = reinterpret_cast<const float4*>(tgt);

    const int tid    = blockIdx.x * blockDim.x + threadIdx.x;
    const int stride = gridDim.x * blockDim.x;
    const int total4 = n * 4;           // one float4 = quarter of a row

    // Fully coalesced: warp reads 512B contiguous per LDG (nL=4, the floor).
    // Each lane adds its PARTIAL row-dot into dots[bid]; the 4 lanes of a row
    // hit the same bid, so the global segment sums are exact.
#pragma unroll 4
    for (int f = tid; f < total4; f += stride) {
        float4 x = inp4[f];
        float4 y = tgt4[f];
        int bid = batch[f >> 2] & (B_GRAPHS - 1);   // quad-broadcast load

        float sq = 0.0f;
        sq = fmaf(x.x, x.x, sq); sq = fmaf(x.y, x.y, sq);
        sq = fmaf(x.z, x.z, sq); sq = fmaf(x.w, x.w, sq);
        sq = fmaf(y.x, y.x, sq); sq = fmaf(y.y, y.y, sq);
        sq = fmaf(y.z, y.z, sq); sq = fmaf(y.w, y.w, sq);
        base += sq;

        float d = 0.0f;
        d = fmaf(x.x, y.x, d); d = fmaf(x.y, y.y, d);
        d = fmaf(x.z, y.z, d); d = fmaf(x.w, y.w, d);

        // predicated adds (unrolled) — no local-memory spill
#pragma unroll
        for (int b = 0; b < B_GRAPHS; b++)
            if (bid == b) dots[b] += d;
    }

    // ----- block reduce of the 9 values -----
    float vals[NVALS];
    vals[0] = base;
#pragma unroll
    for (int b = 0; b < B_GRAPHS; b++) vals[b + 1] = dots[b];

#pragma unroll
    for (int k = 0; k < NVALS; k++) {
#pragma unroll
        for (int off = 16; off > 0; off >>= 1)
            vals[k] += __shfl_down_sync(0xFFFFFFFFu, vals[k], off);
    }

    __shared__ float smem[ACC_THREADS / 32][NVALS];
    __shared__ int s_is_last;
    int warp = threadIdx.x >> 5;
    int lane = threadIdx.x & 31;
    if (lane == 0) {
#pragma unroll
        for (int k = 0; k < NVALS; k++) smem[warp][k] = vals[k];
    }
    __syncthreads();

    if (threadIdx.x == 0) {
        float o[NVALS];
#pragma unroll
        for (int k = 0; k < NVALS; k++) o[k] = smem[0][k];
#pragma unroll
        for (int w = 1; w < ACC_THREADS / 32; w++) {
#pragma unroll
            for (int k = 0; k < NVALS; k++) o[k] += smem[w][k];
        }
#pragma unroll
        for (int k = 0; k < NVALS; k++)
            g_partials[k][blockIdx.x] = o[k];

        __threadfence();
        unsigned int ticket = atomicAdd(&g_ticket, 1u);
        s_is_last = (ticket == (unsigned)(gridDim.x - 1)) ? 1 : 0;
    }
    __syncthreads();

    if (!s_is_last) return;

    // ----- last block: reduce all partials (coalesced float4 reads) -----
    __threadfence();   // acquire side of the ticket handshake
    float fv[NVALS];
#pragma unroll
    for (int k = 0; k < NVALS; k++) fv[k] = 0.0f;

    for (int r4 = threadIdx.x; r4 < ACC_BLOCKS / 4; r4 += ACC_THREADS) {
#pragma unroll
        for (int k = 0; k < NVALS; k++) {
            float4 v = reinterpret_cast<const float4*>(g_partials[k])[r4];
            fv[k] += (v.x + v.y) + (v.z + v.w);
        }
    }

#pragma unroll
    for (int k = 0; k < NVALS; k++) {
#pragma unroll
        for (int off = 16; off > 0; off >>= 1)
            fv[k] += __shfl_down_sync(0xFFFFFFFFu, fv[k], off);
    }

    __syncthreads();   // smem reuse
    if (lane == 0) {
#pragma unroll
        for (int k = 0; k < NVALS; k++) smem[warp][k] = fv[k];
    }
    __syncthreads();

    if (threadIdx.x == 0) {
        float acc[NVALS];
#pragma unroll
        for (int k = 0; k < NVALS; k++) acc[k] = smem[0][k];
#pragma unroll
        for (int w = 1; w < ACC_THREADS / 32; w++) {
#pragma unroll
            for (int k = 0; k < NVALS; k++) acc[k] += smem[w][k];
        }
        // min over all 2^B sign combos == base - 2 * sum_b |dot_b|
        float s = 0.0f;
#pragma unroll
        for (int b = 0; b < B_GRAPHS; b++) s += fabsf(acc[b + 1]);
        out[0] = acc[0] - 2.0f * s;
        g_ticket = 0u;   // reset for next graph replay
    }
}

extern "C" void kernel_launch(void* const* d_in, const int* in_sizes, int n_in,
                              void* d_out, int out_size)
{
    const float* inp   = (const float*)d_in[0];
    const float* tgt   = (const float*)d_in[1];
    const int*   batch = (const int*)d_in[2];
    float* out = (float*)d_out;

    int n = in_sizes[2];  // number of nodes (batch vector length)

    fused_kernel<<<ACC_BLOCKS, ACC_THREADS>>>(inp, tgt, batch, out, n);
}

// round 7
// speedup vs baseline: 1.5773x; 1.0470x over previous
#include <cuda_runtime.h>
#include <cuda_bf16.h>
#include <cstdint>

// Problem constants (fixed by the reference generator)
#define F_DIM 16
#define B_GRAPHS 8
#define NVALS 9               // base + 8 segment dots
#define ACC_BLOCKS 2048
#define ACC_THREADS 256

// Per-block partials, transposed: g_partials[k][block]. Fully rewritten each
// launch -> no zeroing needed.
__device__ float g_partials[NVALS][ACC_BLOCKS];
// Ticket counter: starts 0 at module load; last block resets it to 0 every
// launch -> deterministic across graph replays.
__device__ unsigned int g_ticket;

__global__ __launch_bounds__(ACC_THREADS) void fused_kernel(
    const float* __restrict__ inp,
    const float* __restrict__ tgt,
    const int* __restrict__ batch,
    float* __restrict__ out,
    int n)
{
    float base = 0.0f;
    float dots[B_GRAPHS];
#pragma unroll
    for (int b = 0; b < B_GRAPHS; b++) dots[b] = 0.0f;

    const float4* __restrict__ inp4 = reinterpret_cast<const float4*>(inp);
    const float4* __restrict__ tgt4 = reinterpret_cast<const float4*>(tgt);

    const int tid    = blockIdx.x * blockDim.x + threadIdx.x;
    const int stride = gridDim.x * blockDim.x;
    const int total4 = n * 4;           // one float4 = quarter of a row

    // Fully coalesced: warp reads 512B contiguous per LDG (nL=4, the floor).
    // Each lane adds its PARTIAL row-dot into dots[bid]; the 4 lanes of a row
    // hit the same bid, so the global segment sums are exact.
    // __ldcs: read-once streaming data, evict-first in L2.
#pragma unroll 8
    for (int f = tid; f < total4; f += stride) {
        float4 x = __ldcs(inp4 + f);
        float4 y = __ldcs(tgt4 + f);
        int bid = __ldg(batch + (f >> 2)) & (B_GRAPHS - 1);  // quad-broadcast

        float sq = 0.0f;
        sq = fmaf(x.x, x.x, sq); sq = fmaf(x.y, x.y, sq);
        sq = fmaf(x.z, x.z, sq); sq = fmaf(x.w, x.w, sq);
        sq = fmaf(y.x, y.x, sq); sq = fmaf(y.y, y.y, sq);
        sq = fmaf(y.z, y.z, sq); sq = fmaf(y.w, y.w, sq);
        base += sq;

        float d = 0.0f;
        d = fmaf(x.x, y.x, d); d = fmaf(x.y, y.y, d);
        d = fmaf(x.z, y.z, d); d = fmaf(x.w, y.w, d);

        // predicated adds (unrolled) — no local-memory spill
#pragma unroll
        for (int b = 0; b < B_GRAPHS; b++)
            if (bid == b) dots[b] += d;
    }

    // ----- block reduce of the 9 values -----
    float vals[NVALS];
    vals[0] = base;
#pragma unroll
    for (int b = 0; b < B_GRAPHS; b++) vals[b + 1] = dots[b];

#pragma unroll
    for (int k = 0; k < NVALS; k++) {
#pragma unroll
        for (int off = 16; off > 0; off >>= 1)
            vals[k] += __shfl_down_sync(0xFFFFFFFFu, vals[k], off);
    }

    __shared__ float smem[ACC_THREADS / 32][NVALS];
    __shared__ int s_is_last;
    int warp = threadIdx.x >> 5;
    int lane = threadIdx.x & 31;
    if (lane == 0) {
#pragma unroll
        for (int k = 0; k < NVALS; k++) smem[warp][k] = vals[k];
    }
    __syncthreads();

    if (threadIdx.x == 0) {
        float o[NVALS];
#pragma unroll
        for (int k = 0; k < NVALS; k++) o[k] = smem[0][k];
#pragma unroll
        for (int w = 1; w < ACC_THREADS / 32; w++) {
#pragma unroll
            for (int k = 0; k < NVALS; k++) o[k] += smem[w][k];
        }
#pragma unroll
        for (int k = 0; k < NVALS; k++)
            g_partials[k][blockIdx.x] = o[k];

        __threadfence();
        unsigned int ticket = atomicAdd(&g_ticket, 1u);
        s_is_last = (ticket == (unsigned)(gridDim.x - 1)) ? 1 : 0;
    }
    __syncthreads();

    if (!s_is_last) return;

    // ----- last block: reduce all partials (coalesced float4 reads) -----
    __threadfence();   // acquire side of the ticket handshake
    float fv[NVALS];
#pragma unroll
    for (int k = 0; k < NVALS; k++) fv[k] = 0.0f;

    for (int r4 = threadIdx.x; r4 < ACC_BLOCKS / 4; r4 += ACC_THREADS) {
#pragma unroll
        for (int k = 0; k < NVALS; k++) {
            float4 v = reinterpret_cast<const float4*>(g_partials[k])[r4];
            fv[k] += (v.x + v.y) + (v.z + v.w);
        }
    }

#pragma unroll
    for (int k = 0; k < NVALS; k++) {
#pragma unroll
        for (int off = 16; off > 0; off >>= 1)
            fv[k] += __shfl_down_sync(0xFFFFFFFFu, fv[k], off);
    }

    __syncthreads();   // smem reuse
    if (lane == 0) {
#pragma unroll
        for (int k = 0; k < NVALS; k++) smem[warp][k] = fv[k];
    }
    __syncthreads();

    if (threadIdx.x == 0) {
        float acc[NVALS];
#pragma unroll
        for (int k = 0; k < NVALS; k++) acc[k] = smem[0][k];
#pragma unroll
        for (int w = 1; w < ACC_THREADS / 32; w++) {
#pragma unroll
            for (int k = 0; k < NVALS; k++) acc[k] += smem[w][k];
        }
        // min over all 2^B sign combos == base - 2 * sum_b |dot_b|
        float s = 0.0f;
#pragma unroll
        for (int b = 0; b < B_GRAPHS; b++) s += fabsf(acc[b + 1]);
        out[0] = acc[0] - 2.0f * s;
        g_ticket = 0u;   // reset for next graph replay
    }
}

extern "C" void kernel_launch(void* const* d_in, const int* in_sizes, int n_in,
                              void* d_out, int out_size)
{
    const float* inp   = (const float*)d_in[0];
    const float* tgt   = (const float*)d_in[1];
    const int*   batch = (const int*)d_in[2];
    float* out = (float*)d_out;

    int n = in_sizes[2];  // number of nodes (batch vector length)

    fused_kernel<<<ACC_BLOCKS, ACC_THREADS>>>(inp, tgt, batch, out, n);
}